// round 12
// baseline (speedup 1.0000x reference)
#include <cuda_runtime.h>
#include <stdint.h>

// Problem constants (fixed by the dataset config)
#define CIN     32
#define COUT    64
#define DO_     48
#define NOFF    27
#define W_ELEMS (3*3*3*CIN*COUT)   // 55296

// Kernel tiling
#define TILE_V   384
#define NTHREADS 256
#define NWARPS   (NTHREADS/32)

#define SMEM_FEAT_BYTES  (TILE_V * CIN * 4)          // 49152
#define SMEM_LIST_BYTES  (NOFF * TILE_V * 4)         // 41472
#define SMEM_CNT_BYTES   (32 * 4)                    // 128 (27 counters + pad)
#define SMEM_BYTES       (SMEM_FEAT_BYTES + SMEM_LIST_BYTES + SMEM_CNT_BYTES)

// ---------------------------------------------------------------------------
// f32x2 packed helpers (Blackwell: FFMA2 only reachable via PTX fma.rn.f32x2)
// ---------------------------------------------------------------------------
__device__ __forceinline__ unsigned long long pack2(float lo, float hi) {
    unsigned long long r;
    asm("mov.b64 %0, {%1, %2};" : "=l"(r) : "f"(lo), "f"(hi));
    return r;
}
__device__ __forceinline__ unsigned long long fma2(unsigned long long a,
                                                   unsigned long long b,
                                                   unsigned long long c) {
    unsigned long long d;
    asm("fma.rn.f32x2 %0, %1, %2, %3;" : "=l"(d) : "l"(a), "l"(b), "l"(c));
    return d;
}
__device__ __forceinline__ float lo_f(unsigned long long v) {
    return __uint_as_float((unsigned)(v & 0xffffffffull));
}
__device__ __forceinline__ float hi_f(unsigned long long v) {
    return __uint_as_float((unsigned)(v >> 32));
}
// Vector reduction, no return (sm_90+): 1 instruction updates 2 adjacent floats
__device__ __forceinline__ void red2(float* p, float a, float b) {
    asm volatile("red.global.add.v2.f32 [%0], {%1, %2};"
                 :: "l"(p), "f"(a), "f"(b) : "memory");
}

// ---------------------------------------------------------------------------
// Zero the output buffer (harness poisons it to 0xAA)
// ---------------------------------------------------------------------------
__global__ void zero_kernel(float* __restrict__ out, int n) {
    int n4 = n >> 2;
    float4 z = make_float4(0.f, 0.f, 0.f, 0.f);
    for (int i = blockIdx.x * blockDim.x + threadIdx.x; i < n4;
         i += gridDim.x * blockDim.x) {
        reinterpret_cast<float4*>(out)[i] = z;
    }
    // scalar tail (out_size is 64-divisible in practice, but stay safe)
    if (blockIdx.x == 0 && threadIdx.x < (n & 3)) {
        out[(n4 << 2) + threadIdx.x] = 0.f;
    }
}

// ---------------------------------------------------------------------------
// Main sparse-conv kernel:
//   phase 1: stage 384 voxels' features in smem, build per-offset compacted
//            (voxel, out_idx) lists via warp-aggregated smem atomics
//   phase 2: each warp owns offsets (round-robin), W register-resident as
//            f32x2 k-pairs, 2 voxels/iter (4 acc chains), red.v2 epilogue
// ---------------------------------------------------------------------------
__global__ void __launch_bounds__(NTHREADS, 2)
spconv_kernel(const float* __restrict__ feats,
              const int*   __restrict__ coors,
              const float* __restrict__ Wg,
              float*       __restrict__ out,
              int n)
{
    extern __shared__ char smem[];
    float* s_feat  = reinterpret_cast<float*>(smem);
    int*   s_list  = reinterpret_cast<int*>(smem + SMEM_FEAT_BYTES);
    int*   s_count = reinterpret_cast<int*>(smem + SMEM_FEAT_BYTES + SMEM_LIST_BYTES);

    const int tid  = threadIdx.x;
    const int lane = tid & 31;
    const int wid  = tid >> 5;
    const int v0   = blockIdx.x * TILE_V;
    const int nv   = min(TILE_V, n - v0);

    if (tid < NOFF) s_count[tid] = 0;
    __syncthreads();

    // ---- stage features (contiguous, float4-coalesced) ----
    {
        const float4* fsrc = reinterpret_cast<const float4*>(feats + (size_t)v0 * CIN);
        float4* fdst = reinterpret_cast<float4*>(s_feat);
        const int nf4 = nv * (CIN / 4);
        for (int i = tid; i < nf4; i += NTHREADS) fdst[i] = fsrc[i];
    }

    // ---- build per-offset compacted lists ----
    #pragma unroll
    for (int s = 0; s < (TILE_V + NTHREADS - 1) / NTHREADS; s++) {
        const int vi  = s * NTHREADS + tid;
        const bool act = (vi < nv);
        int b = 0, z = 0, y = 0, x = 0;
        if (act) {
            int4 c = reinterpret_cast<const int4*>(coors)[v0 + vi];
            b = c.x; z = c.y; y = c.z; x = c.w;
        }
        #pragma unroll
        for (int kz = 0; kz < 3; kz++)
        #pragma unroll
        for (int ky = 0; ky < 3; ky++)
        #pragma unroll
        for (int kx = 0; kx < 3; kx++) {
            const int off = (kz * 3 + ky) * 3 + kx;
            const int zn = z + 1 - kz, yn = y + 1 - ky, xn = x + 1 - kx;
            // parity test also rejects zn==-1 (bit0 set); >>1 of -1 then maps
            // to huge unsigned → rejected by bounds, matching jnp semantics.
            bool valid = act && (((zn | yn | xn) & 1) == 0);
            const int zo = zn >> 1, yo = yn >> 1, xo = xn >> 1;
            valid = valid && ((unsigned)zo < DO_) && ((unsigned)yo < DO_) &&
                    ((unsigned)xo < DO_);
            const int idx = ((b * DO_ + zo) * DO_ + yo) * DO_ + xo;

            const unsigned m = __ballot_sync(0xffffffffu, valid);
            if (m) {
                const int leader = __ffs(m) - 1;
                int base = 0;
                if (lane == leader) base = atomicAdd(&s_count[off], __popc(m));
                base = __shfl_sync(0xffffffffu, base, leader);
                if (valid) {
                    const int pos = base + __popc(m & ((1u << lane) - 1u));
                    s_list[off * TILE_V + pos] = (vi << 18) | idx;
                }
            }
        }
    }
    __syncthreads();

    // ---- compute: warp-per-offset round robin ----
    const int c2 = lane * 2;  // this lane's two adjacent output channels
    for (int off = wid; off < NOFF; off += NWARPS) {
        const int cnt = s_count[off];
        if (cnt == 0) continue;

        // W register-resident: w0[j] = {W[2j][c2],   W[2j+1][c2]}
        //                      w1[j] = {W[2j][c2+1], W[2j+1][c2+1]}
        const float* Wo = Wg + off * (CIN * COUT);
        unsigned long long w0[CIN / 2], w1[CIN / 2];
        #pragma unroll
        for (int j = 0; j < CIN / 2; j++) {
            float2 a  = *reinterpret_cast<const float2*>(Wo + (2 * j) * COUT + c2);
            float2 bq = *reinterpret_cast<const float2*>(Wo + (2 * j + 1) * COUT + c2);
            w0[j] = pack2(a.x, bq.x);
            w1[j] = pack2(a.y, bq.y);
        }

        const int* lst = s_list + off * TILE_V;
        for (int e = 0; e < cnt; e += 2) {
            const int  e0   = lst[e];
            const bool has2 = (e + 1) < cnt;
            const int  e1   = has2 ? lst[e + 1] : e0;
            const int vA = e0 >> 18, oA = e0 & 0x3ffff;
            const int vB = e1 >> 18, oB = e1 & 0x3ffff;
            const ulonglong2* fA =
                reinterpret_cast<const ulonglong2*>(s_feat + vA * CIN);
            const ulonglong2* fB =
                reinterpret_cast<const ulonglong2*>(s_feat + vB * CIN);

            unsigned long long a0 = 0ull, a1 = 0ull, b0 = 0ull, b1 = 0ull;
            #pragma unroll
            for (int q = 0; q < CIN / 4; q++) {
                const ulonglong2 fa = fA[q];   // {f[4q],f[4q+1]},{f[4q+2],f[4q+3]}
                const ulonglong2 fb = fB[q];
                a0 = fma2(fa.x, w0[2 * q],     a0);
                a1 = fma2(fa.x, w1[2 * q],     a1);
                a0 = fma2(fa.y, w0[2 * q + 1], a0);
                a1 = fma2(fa.y, w1[2 * q + 1], a1);
                b0 = fma2(fb.x, w0[2 * q],     b0);
                b1 = fma2(fb.x, w1[2 * q],     b1);
                b0 = fma2(fb.y, w0[2 * q + 1], b0);
                b1 = fma2(fb.y, w1[2 * q + 1], b1);
            }
            // fold even-k / odd-k halves, then one v2 reduction per voxel
            const float rA0 = lo_f(a0) + hi_f(a0);
            const float rA1 = lo_f(a1) + hi_f(a1);
            red2(out + (size_t)oA * COUT + c2, rA0, rA1);
            if (has2) {
                const float rB0 = lo_f(b0) + hi_f(b0);
                const float rB1 = lo_f(b1) + hi_f(b1);
                red2(out + (size_t)oB * COUT + c2, rB0, rB1);
            }
        }
    }
}

// ---------------------------------------------------------------------------
// Launch
// ---------------------------------------------------------------------------
extern "C" void kernel_launch(void* const* d_in, const int* in_sizes, int n_in,
                              void* d_out, int out_size)
{
    // Identify inputs by size: W == 55296; batch_size == 1 elem;
    // of the remaining two, features (N*32) > coors (N*4).
    int wi = -1;
    for (int i = 0; i < n_in; i++)
        if (in_sizes[i] == W_ELEMS) { wi = i; break; }
    int cand[8]; int nc = 0;
    for (int i = 0; i < n_in; i++) {
        if (i == wi || in_sizes[i] <= 1) continue;
        if (nc < 8) cand[nc++] = i;
    }
    int fi = cand[0], ci = cand[1];
    if (nc >= 2 && in_sizes[cand[1]] > in_sizes[cand[0]]) { fi = cand[1]; ci = cand[0]; }

    const float* feats = reinterpret_cast<const float*>(d_in[fi]);
    const int*   coors = reinterpret_cast<const int*>(d_in[ci]);
    const float* Wg    = reinterpret_cast<const float*>(d_in[wi]);
    float*       out   = reinterpret_cast<float*>(d_out);
    const int n = in_sizes[fi] / CIN;

    cudaFuncSetAttribute(spconv_kernel,
                         cudaFuncAttributeMaxDynamicSharedMemorySize, SMEM_BYTES);

    // 1) zero the output (poisoned by harness)
    {
        int n4 = out_size >> 2;
        int blocks = (n4 + 255) / 256;
        if (blocks > 16384) blocks = 16384;
        if (blocks < 1) blocks = 1;
        zero_kernel<<<blocks, 256>>>(out, out_size);
    }

    // 2) sparse conv
    {
        const int blocks = (n + TILE_V - 1) / TILE_V;
        spconv_kernel<<<blocks, NTHREADS, SMEM_BYTES>>>(feats, coors, Wg, out, n);
    }
}

// round 13
// speedup vs baseline: 1.0007x; 1.0007x over previous
#include <cuda_runtime.h>
#include <stdint.h>

// Problem constants (fixed by the dataset config)
#define CIN     32
#define COUT    64
#define DO_     48
#define NOFF    27
#define W_ELEMS (3*3*3*CIN*COUT)   // 55296

// Kernel tiling
#define TILE_V   384
#define NTHREADS 256
#define NWARPS   (NTHREADS/32)

#define SMEM_FEAT_BYTES  (TILE_V * CIN * 4)          // 49152
#define SMEM_LIST_BYTES  (NOFF * TILE_V * 4)         // 41472
#define SMEM_CNT_BYTES   (32 * 4)                    // 128 (27 counters + pad)
#define SMEM_BYTES       (SMEM_FEAT_BYTES + SMEM_LIST_BYTES + SMEM_CNT_BYTES)

// ---------------------------------------------------------------------------
// f32x2 packed helpers (Blackwell: FFMA2 only reachable via PTX fma.rn.f32x2)
// ---------------------------------------------------------------------------
__device__ __forceinline__ unsigned long long pack2(float lo, float hi) {
    unsigned long long r;
    asm("mov.b64 %0, {%1, %2};" : "=l"(r) : "f"(lo), "f"(hi));
    return r;
}
__device__ __forceinline__ unsigned long long fma2(unsigned long long a,
                                                   unsigned long long b,
                                                   unsigned long long c) {
    unsigned long long d;
    asm("fma.rn.f32x2 %0, %1, %2, %3;" : "=l"(d) : "l"(a), "l"(b), "l"(c));
    return d;
}
__device__ __forceinline__ float lo_f(unsigned long long v) {
    return __uint_as_float((unsigned)(v & 0xffffffffull));
}
__device__ __forceinline__ float hi_f(unsigned long long v) {
    return __uint_as_float((unsigned)(v >> 32));
}
// Vector reduction, no return (sm_90+): 1 instruction updates 2 adjacent floats
__device__ __forceinline__ void red2(float* p, float a, float b) {
    asm volatile("red.global.add.v2.f32 [%0], {%1, %2};"
                 :: "l"(p), "f"(a), "f"(b) : "memory");
}

// ---------------------------------------------------------------------------
// Zero the output buffer (harness poisons it to 0xAA)
// ---------------------------------------------------------------------------
__global__ void zero_kernel(float* __restrict__ out, int n) {
    int n4 = n >> 2;
    float4 z = make_float4(0.f, 0.f, 0.f, 0.f);
    for (int i = blockIdx.x * blockDim.x + threadIdx.x; i < n4;
         i += gridDim.x * blockDim.x) {
        reinterpret_cast<float4*>(out)[i] = z;
    }
    // scalar tail (out_size is 64-divisible in practice, but stay safe)
    if (blockIdx.x == 0 && threadIdx.x < (n & 3)) {
        out[(n4 << 2) + threadIdx.x] = 0.f;
    }
}

// ---------------------------------------------------------------------------
// Main sparse-conv kernel:
//   phase 1: stage 384 voxels' features in smem, build per-offset compacted
//            (voxel, out_idx) lists via warp-aggregated smem atomics
//   phase 2: each warp owns offsets (round-robin), W register-resident as
//            f32x2 k-pairs, 2 voxels/iter (4 acc chains), red.v2 epilogue
// ---------------------------------------------------------------------------
__global__ void __launch_bounds__(NTHREADS, 2)
spconv_kernel(const float* __restrict__ feats,
              const int*   __restrict__ coors,
              const float* __restrict__ Wg,
              float*       __restrict__ out,
              int n)
{
    extern __shared__ char smem[];
    float* s_feat  = reinterpret_cast<float*>(smem);
    int*   s_list  = reinterpret_cast<int*>(smem + SMEM_FEAT_BYTES);
    int*   s_count = reinterpret_cast<int*>(smem + SMEM_FEAT_BYTES + SMEM_LIST_BYTES);

    const int tid  = threadIdx.x;
    const int lane = tid & 31;
    const int wid  = tid >> 5;
    const int v0   = blockIdx.x * TILE_V;
    const int nv   = min(TILE_V, n - v0);

    if (tid < NOFF) s_count[tid] = 0;
    __syncthreads();

    // ---- stage features (contiguous, float4-coalesced) ----
    {
        const float4* fsrc = reinterpret_cast<const float4*>(feats + (size_t)v0 * CIN);
        float4* fdst = reinterpret_cast<float4*>(s_feat);
        const int nf4 = nv * (CIN / 4);
        for (int i = tid; i < nf4; i += NTHREADS) fdst[i] = fsrc[i];
    }

    // ---- build per-offset compacted lists ----
    #pragma unroll
    for (int s = 0; s < (TILE_V + NTHREADS - 1) / NTHREADS; s++) {
        const int vi  = s * NTHREADS + tid;
        const bool act = (vi < nv);
        int b = 0, z = 0, y = 0, x = 0;
        if (act) {
            int4 c = reinterpret_cast<const int4*>(coors)[v0 + vi];
            b = c.x; z = c.y; y = c.z; x = c.w;
        }
        #pragma unroll
        for (int kz = 0; kz < 3; kz++)
        #pragma unroll
        for (int ky = 0; ky < 3; ky++)
        #pragma unroll
        for (int kx = 0; kx < 3; kx++) {
            const int off = (kz * 3 + ky) * 3 + kx;
            const int zn = z + 1 - kz, yn = y + 1 - ky, xn = x + 1 - kx;
            // parity test also rejects zn==-1 (bit0 set); >>1 of -1 then maps
            // to huge unsigned → rejected by bounds, matching jnp semantics.
            bool valid = act && (((zn | yn | xn) & 1) == 0);
            const int zo = zn >> 1, yo = yn >> 1, xo = xn >> 1;
            valid = valid && ((unsigned)zo < DO_) && ((unsigned)yo < DO_) &&
                    ((unsigned)xo < DO_);
            const int idx = ((b * DO_ + zo) * DO_ + yo) * DO_ + xo;

            const unsigned m = __ballot_sync(0xffffffffu, valid);
            if (m) {
                const int leader = __ffs(m) - 1;
                int base = 0;
                if (lane == leader) base = atomicAdd(&s_count[off], __popc(m));
                base = __shfl_sync(0xffffffffu, base, leader);
                if (valid) {
                    const int pos = base + __popc(m & ((1u << lane) - 1u));
                    s_list[off * TILE_V + pos] = (vi << 18) | idx;
                }
            }
        }
    }
    __syncthreads();

    // ---- compute: warp-per-offset round robin ----
    const int c2 = lane * 2;  // this lane's two adjacent output channels
    for (int off = wid; off < NOFF; off += NWARPS) {
        const int cnt = s_count[off];
        if (cnt == 0) continue;

        // W register-resident: w0[j] = {W[2j][c2],   W[2j+1][c2]}
        //                      w1[j] = {W[2j][c2+1], W[2j+1][c2+1]}
        const float* Wo = Wg + off * (CIN * COUT);
        unsigned long long w0[CIN / 2], w1[CIN / 2];
        #pragma unroll
        for (int j = 0; j < CIN / 2; j++) {
            float2 a  = *reinterpret_cast<const float2*>(Wo + (2 * j) * COUT + c2);
            float2 bq = *reinterpret_cast<const float2*>(Wo + (2 * j + 1) * COUT + c2);
            w0[j] = pack2(a.x, bq.x);
            w1[j] = pack2(a.y, bq.y);
        }

        const int* lst = s_list + off * TILE_V;
        for (int e = 0; e < cnt; e += 2) {
            const int  e0   = lst[e];
            const bool has2 = (e + 1) < cnt;
            const int  e1   = has2 ? lst[e + 1] : e0;
            const int vA = e0 >> 18, oA = e0 & 0x3ffff;
            const int vB = e1 >> 18, oB = e1 & 0x3ffff;
            const ulonglong2* fA =
                reinterpret_cast<const ulonglong2*>(s_feat + vA * CIN);
            const ulonglong2* fB =
                reinterpret_cast<const ulonglong2*>(s_feat + vB * CIN);

            unsigned long long a0 = 0ull, a1 = 0ull, b0 = 0ull, b1 = 0ull;
            #pragma unroll
            for (int q = 0; q < CIN / 4; q++) {
                const ulonglong2 fa = fA[q];   // {f[4q],f[4q+1]},{f[4q+2],f[4q+3]}
                const ulonglong2 fb = fB[q];
                a0 = fma2(fa.x, w0[2 * q],     a0);
                a1 = fma2(fa.x, w1[2 * q],     a1);
                a0 = fma2(fa.y, w0[2 * q + 1], a0);
                a1 = fma2(fa.y, w1[2 * q + 1], a1);
                b0 = fma2(fb.x, w0[2 * q],     b0);
                b1 = fma2(fb.x, w1[2 * q],     b1);
                b0 = fma2(fb.y, w0[2 * q + 1], b0);
                b1 = fma2(fb.y, w1[2 * q + 1], b1);
            }
            // fold even-k / odd-k halves, then one v2 reduction per voxel
            const float rA0 = lo_f(a0) + hi_f(a0);
            const float rA1 = lo_f(a1) + hi_f(a1);
            red2(out + (size_t)oA * COUT + c2, rA0, rA1);
            if (has2) {
                const float rB0 = lo_f(b0) + hi_f(b0);
                const float rB1 = lo_f(b1) + hi_f(b1);
                red2(out + (size_t)oB * COUT + c2, rB0, rB1);
            }
        }
    }
}

// ---------------------------------------------------------------------------
// Launch
// ---------------------------------------------------------------------------
extern "C" void kernel_launch(void* const* d_in, const int* in_sizes, int n_in,
                              void* d_out, int out_size)
{
    // Identify inputs by size: W == 55296; batch_size == 1 elem;
    // of the remaining two, features (N*32) > coors (N*4).
    int wi = -1;
    for (int i = 0; i < n_in; i++)
        if (in_sizes[i] == W_ELEMS) { wi = i; break; }
    int cand[8]; int nc = 0;
    for (int i = 0; i < n_in; i++) {
        if (i == wi || in_sizes[i] <= 1) continue;
        if (nc < 8) cand[nc++] = i;
    }
    int fi = cand[0], ci = cand[1];
    if (nc >= 2 && in_sizes[cand[1]] > in_sizes[cand[0]]) { fi = cand[1]; ci = cand[0]; }

    const float* feats = reinterpret_cast<const float*>(d_in[fi]);
    const int*   coors = reinterpret_cast<const int*>(d_in[ci]);
    const float* Wg    = reinterpret_cast<const float*>(d_in[wi]);
    float*       out   = reinterpret_cast<float*>(d_out);
    const int n = in_sizes[fi] / CIN;

    cudaFuncSetAttribute(spconv_kernel,
                         cudaFuncAttributeMaxDynamicSharedMemorySize, SMEM_BYTES);

    // 1) zero the output (poisoned by harness)
    {
        int n4 = out_size >> 2;
        int blocks = (n4 + 255) / 256;
        if (blocks > 16384) blocks = 16384;
        if (blocks < 1) blocks = 1;
        zero_kernel<<<blocks, 256>>>(out, out_size);
    }

    // 2) sparse conv
    {
        const int blocks = (n + TILE_V - 1) / TILE_V;
        spconv_kernel<<<blocks, NTHREADS, SMEM_BYTES>>>(feats, coors, Wg, out, n);
    }
}

// round 14
// speedup vs baseline: 1.0054x; 1.0047x over previous
#include <cuda_runtime.h>
#include <stdint.h>

// Problem constants (fixed by the dataset config)
#define CIN     32
#define COUT    64
#define DO_     48
#define NOFF    27
#define W_ELEMS (3*3*3*CIN*COUT)   // 55296

// Kernel tiling
#define TILE_V   384
#define NTHREADS 256
#define NWARPS   (NTHREADS/32)

#define SMEM_FEAT_BYTES  (TILE_V * CIN * 4)          // 49152
#define SMEM_LIST_BYTES  (NOFF * TILE_V * 4)         // 41472
#define SMEM_CNT_BYTES   (32 * 4)                    // 128 (27 counters + pad)
#define SMEM_BYTES       (SMEM_FEAT_BYTES + SMEM_LIST_BYTES + SMEM_CNT_BYTES)

// ---------------------------------------------------------------------------
// f32x2 packed helpers (Blackwell: FFMA2 only reachable via PTX fma.rn.f32x2)
// ---------------------------------------------------------------------------
__device__ __forceinline__ unsigned long long pack2(float lo, float hi) {
    unsigned long long r;
    asm("mov.b64 %0, {%1, %2};" : "=l"(r) : "f"(lo), "f"(hi));
    return r;
}
__device__ __forceinline__ unsigned long long fma2(unsigned long long a,
                                                   unsigned long long b,
                                                   unsigned long long c) {
    unsigned long long d;
    asm("fma.rn.f32x2 %0, %1, %2, %3;" : "=l"(d) : "l"(a), "l"(b), "l"(c));
    return d;
}
__device__ __forceinline__ float lo_f(unsigned long long v) {
    return __uint_as_float((unsigned)(v & 0xffffffffull));
}
__device__ __forceinline__ float hi_f(unsigned long long v) {
    return __uint_as_float((unsigned)(v >> 32));
}
// Vector reduction, no return (sm_90+): 1 instruction updates 2 adjacent floats
__device__ __forceinline__ void red2(float* p, float a, float b) {
    asm volatile("red.global.add.v2.f32 [%0], {%1, %2};"
                 :: "l"(p), "f"(a), "f"(b) : "memory");
}

// ---------------------------------------------------------------------------
// Zero the output buffer (harness poisons it to 0xAA)
// ---------------------------------------------------------------------------
__global__ void zero_kernel(float* __restrict__ out, int n) {
    int n4 = n >> 2;
    float4 z = make_float4(0.f, 0.f, 0.f, 0.f);
    for (int i = blockIdx.x * blockDim.x + threadIdx.x; i < n4;
         i += gridDim.x * blockDim.x) {
        reinterpret_cast<float4*>(out)[i] = z;
    }
    // scalar tail (out_size is 64-divisible in practice, but stay safe)
    if (blockIdx.x == 0 && threadIdx.x < (n & 3)) {
        out[(n4 << 2) + threadIdx.x] = 0.f;
    }
}

// ---------------------------------------------------------------------------
// Main sparse-conv kernel:
//   phase 1: stage 384 voxels' features in smem, build per-offset compacted
//            (voxel, out_idx) lists via warp-aggregated smem atomics
//   phase 2: each warp owns offsets (round-robin), W register-resident as
//            f32x2 k-pairs, 2 voxels/iter (4 acc chains), red.v2 epilogue
// ---------------------------------------------------------------------------
__global__ void __launch_bounds__(NTHREADS, 2)
spconv_kernel(const float* __restrict__ feats,
              const int*   __restrict__ coors,
              const float* __restrict__ Wg,
              float*       __restrict__ out,
              int n)
{
    extern __shared__ char smem[];
    float* s_feat  = reinterpret_cast<float*>(smem);
    int*   s_list  = reinterpret_cast<int*>(smem + SMEM_FEAT_BYTES);
    int*   s_count = reinterpret_cast<int*>(smem + SMEM_FEAT_BYTES + SMEM_LIST_BYTES);

    const int tid  = threadIdx.x;
    const int lane = tid & 31;
    const int wid  = tid >> 5;
    const int v0   = blockIdx.x * TILE_V;
    const int nv   = min(TILE_V, n - v0);

    if (tid < NOFF) s_count[tid] = 0;
    __syncthreads();

    // ---- stage features (contiguous, float4-coalesced) ----
    {
        const float4* fsrc = reinterpret_cast<const float4*>(feats + (size_t)v0 * CIN);
        float4* fdst = reinterpret_cast<float4*>(s_feat);
        const int nf4 = nv * (CIN / 4);
        for (int i = tid; i < nf4; i += NTHREADS) fdst[i] = fsrc[i];
    }

    // ---- build per-offset compacted lists ----
    #pragma unroll
    for (int s = 0; s < (TILE_V + NTHREADS - 1) / NTHREADS; s++) {
        const int vi  = s * NTHREADS + tid;
        const bool act = (vi < nv);
        int b = 0, z = 0, y = 0, x = 0;
        if (act) {
            int4 c = reinterpret_cast<const int4*>(coors)[v0 + vi];
            b = c.x; z = c.y; y = c.z; x = c.w;
        }
        #pragma unroll
        for (int kz = 0; kz < 3; kz++)
        #pragma unroll
        for (int ky = 0; ky < 3; ky++)
        #pragma unroll
        for (int kx = 0; kx < 3; kx++) {
            const int off = (kz * 3 + ky) * 3 + kx;
            const int zn = z + 1 - kz, yn = y + 1 - ky, xn = x + 1 - kx;
            // parity test also rejects zn==-1 (bit0 set); >>1 of -1 then maps
            // to huge unsigned → rejected by bounds, matching jnp semantics.
            bool valid = act && (((zn | yn | xn) & 1) == 0);
            const int zo = zn >> 1, yo = yn >> 1, xo = xn >> 1;
            valid = valid && ((unsigned)zo < DO_) && ((unsigned)yo < DO_) &&
                    ((unsigned)xo < DO_);
            const int idx = ((b * DO_ + zo) * DO_ + yo) * DO_ + xo;

            const unsigned m = __ballot_sync(0xffffffffu, valid);
            if (m) {
                const int leader = __ffs(m) - 1;
                int base = 0;
                if (lane == leader) base = atomicAdd(&s_count[off], __popc(m));
                base = __shfl_sync(0xffffffffu, base, leader);
                if (valid) {
                    const int pos = base + __popc(m & ((1u << lane) - 1u));
                    s_list[off * TILE_V + pos] = (vi << 18) | idx;
                }
            }
        }
    }
    __syncthreads();

    // ---- compute: warp-per-offset round robin ----
    const int c2 = lane * 2;  // this lane's two adjacent output channels
    for (int off = wid; off < NOFF; off += NWARPS) {
        const int cnt = s_count[off];
        if (cnt == 0) continue;

        // W register-resident: w0[j] = {W[2j][c2],   W[2j+1][c2]}
        //                      w1[j] = {W[2j][c2+1], W[2j+1][c2+1]}
        const float* Wo = Wg + off * (CIN * COUT);
        unsigned long long w0[CIN / 2], w1[CIN / 2];
        #pragma unroll
        for (int j = 0; j < CIN / 2; j++) {
            float2 a  = *reinterpret_cast<const float2*>(Wo + (2 * j) * COUT + c2);
            float2 bq = *reinterpret_cast<const float2*>(Wo + (2 * j + 1) * COUT + c2);
            w0[j] = pack2(a.x, bq.x);
            w1[j] = pack2(a.y, bq.y);
        }

        const int* lst = s_list + off * TILE_V;
        for (int e = 0; e < cnt; e += 2) {
            const int  e0   = lst[e];
            const bool has2 = (e + 1) < cnt;
            const int  e1   = has2 ? lst[e + 1] : e0;
            const int vA = e0 >> 18, oA = e0 & 0x3ffff;
            const int vB = e1 >> 18, oB = e1 & 0x3ffff;
            const ulonglong2* fA =
                reinterpret_cast<const ulonglong2*>(s_feat + vA * CIN);
            const ulonglong2* fB =
                reinterpret_cast<const ulonglong2*>(s_feat + vB * CIN);

            unsigned long long a0 = 0ull, a1 = 0ull, b0 = 0ull, b1 = 0ull;
            #pragma unroll
            for (int q = 0; q < CIN / 4; q++) {
                const ulonglong2 fa = fA[q];   // {f[4q],f[4q+1]},{f[4q+2],f[4q+3]}
                const ulonglong2 fb = fB[q];
                a0 = fma2(fa.x, w0[2 * q],     a0);
                a1 = fma2(fa.x, w1[2 * q],     a1);
                a0 = fma2(fa.y, w0[2 * q + 1], a0);
                a1 = fma2(fa.y, w1[2 * q + 1], a1);
                b0 = fma2(fb.x, w0[2 * q],     b0);
                b1 = fma2(fb.x, w1[2 * q],     b1);
                b0 = fma2(fb.y, w0[2 * q + 1], b0);
                b1 = fma2(fb.y, w1[2 * q + 1], b1);
            }
            // fold even-k / odd-k halves, then one v2 reduction per voxel
            const float rA0 = lo_f(a0) + hi_f(a0);
            const float rA1 = lo_f(a1) + hi_f(a1);
            red2(out + (size_t)oA * COUT + c2, rA0, rA1);
            if (has2) {
                const float rB0 = lo_f(b0) + hi_f(b0);
                const float rB1 = lo_f(b1) + hi_f(b1);
                red2(out + (size_t)oB * COUT + c2, rB0, rB1);
            }
        }
    }
}

// ---------------------------------------------------------------------------
// Launch
// ---------------------------------------------------------------------------
extern "C" void kernel_launch(void* const* d_in, const int* in_sizes, int n_in,
                              void* d_out, int out_size)
{
    // Identify inputs by size: W == 55296; batch_size == 1 elem;
    // of the remaining two, features (N*32) > coors (N*4).
    int wi = -1;
    for (int i = 0; i < n_in; i++)
        if (in_sizes[i] == W_ELEMS) { wi = i; break; }
    int cand[8]; int nc = 0;
    for (int i = 0; i < n_in; i++) {
        if (i == wi || in_sizes[i] <= 1) continue;
        if (nc < 8) cand[nc++] = i;
    }
    int fi = cand[0], ci = cand[1];
    if (nc >= 2 && in_sizes[cand[1]] > in_sizes[cand[0]]) { fi = cand[1]; ci = cand[0]; }

    const float* feats = reinterpret_cast<const float*>(d_in[fi]);
    const int*   coors = reinterpret_cast<const int*>(d_in[ci]);
    const float* Wg    = reinterpret_cast<const float*>(d_in[wi]);
    float*       out   = reinterpret_cast<float*>(d_out);
    const int n = in_sizes[fi] / CIN;

    cudaFuncSetAttribute(spconv_kernel,
                         cudaFuncAttributeMaxDynamicSharedMemorySize, SMEM_BYTES);

    // 1) zero the output (poisoned by harness)
    {
        int n4 = out_size >> 2;
        int blocks = (n4 + 255) / 256;
        if (blocks > 16384) blocks = 16384;
        if (blocks < 1) blocks = 1;
        zero_kernel<<<blocks, 256>>>(out, out_size);
    }

    // 2) sparse conv
    {
        const int blocks = (n + TILE_V - 1) / TILE_V;
        spconv_kernel<<<blocks, NTHREADS, SMEM_BYTES>>>(feats, coors, Wg, out, n);
    }
}